// round 10
// baseline (speedup 1.0000x reference)
#include <cuda_runtime.h>
#include <cuda_bf16.h>
#include <math.h>
#include <stdint.h>

// Problem constants
#define BB   2
#define SS   2048
#define DD   1024
#define HH   16
#define DHH  64
#define DMM  4096
#define NTOK (BB*SS)          // 4096
#define EPSLN 1e-5f

typedef __nv_bfloat16  bf16;
typedef __nv_bfloat162 bf162;

// ---------------------------------------------------------------------------
// Device scratch
// ---------------------------------------------------------------------------
__device__ float g_mid[NTOK*DD];
__device__ float g_bias[3*DD];        // concatenated QKV bias
__device__ bf16  g_xh [NTOK*DD];      // split activations (hi)
__device__ bf16  g_xl [NTOK*DD];      // split activations (lo)
__device__ bf16  g_qkvh[NTOK*3*DD];   // fused QKV output (hi)
__device__ bf16  g_qkvl[NTOK*3*DD];   // fused QKV output (lo)
__device__ bf16  g_acth[NTOK*DMM];    // gelu output split (hi)
__device__ bf16  g_actl[NTOK*DMM];    // gelu output split (lo)
__device__ bf16  g_wh [DD*DMM];       // split transposed weight (hi) - reused
__device__ bf16  g_wl [DD*DMM];       // split transposed weight (lo) - reused

// ---------------------------------------------------------------------------
// Helpers
// ---------------------------------------------------------------------------
__device__ __forceinline__ void split2(float x, bf16& h, bf16& l)
{
    h = __float2bfloat16_rn(x);
    l = __float2bfloat16_rn(x - __bfloat162float(h));
}

__device__ __forceinline__ uint32_t cvta_s(const void* p)
{
    return (uint32_t)__cvta_generic_to_shared(p);
}

__device__ __forceinline__ void cp16(uint32_t s, const void* g)
{
    asm volatile("cp.async.cg.shared.global [%0], [%1], 16;" :: "r"(s), "l"(g));
}

__device__ __forceinline__ void ldsm4(unsigned r[4], uint32_t a)
{
    asm volatile("ldmatrix.sync.aligned.m8n8.x4.shared.b16 {%0,%1,%2,%3}, [%4];"
                 : "=r"(r[0]), "=r"(r[1]), "=r"(r[2]), "=r"(r[3]) : "r"(a));
}

__device__ __forceinline__ void ldsm4t(unsigned r[4], uint32_t a)
{
    asm volatile("ldmatrix.sync.aligned.m8n8.x4.trans.shared.b16 {%0,%1,%2,%3}, [%4];"
                 : "=r"(r[0]), "=r"(r[1]), "=r"(r[2]), "=r"(r[3]) : "r"(a));
}

__device__ __forceinline__ void mma16816(float c[4], const unsigned a[4],
                                         const unsigned b[2])
{
    asm volatile(
        "mma.sync.aligned.m16n8k16.row.col.f32.bf16.bf16.f32 "
        "{%0,%1,%2,%3}, {%4,%5,%6,%7}, {%8,%9}, {%0,%1,%2,%3};"
        : "+f"(c[0]), "+f"(c[1]), "+f"(c[2]), "+f"(c[3])
        : "r"(a[0]), "r"(a[1]), "r"(a[2]), "r"(a[3]), "r"(b[0]), "r"(b[1]));
}

__device__ __forceinline__ unsigned packbf(float a, float b)
{
    bf162 t = __floats2bfloat162_rn(a, b);
    return *reinterpret_cast<unsigned*>(&t);
}

__device__ __forceinline__ float gelu_exact(float x)
{
    return 0.5f * x * (1.0f + erff(x * 0.70710678118654752f));
}

// ---------------------------------------------------------------------------
// LayerNorm + split to bf16 hi/lo. One block per row, 256 threads.
// ---------------------------------------------------------------------------
__global__ __launch_bounds__(256)
void ln_split_kernel(const float* __restrict__ x, const float* __restrict__ w,
                     const float* __restrict__ b, bf16* __restrict__ oh,
                     bf16* __restrict__ ol)
{
    __shared__ float red[8];
    __shared__ float bcast;
    const int row = blockIdx.x;
    const int tid = threadIdx.x;
    const int lane = tid & 31, warp = tid >> 5;

    float4 v = ((const float4*)(x + (size_t)row * DD))[tid];

    float s = v.x + v.y + v.z + v.w;
    #pragma unroll
    for (int o = 16; o > 0; o >>= 1) s += __shfl_xor_sync(0xffffffffu, s, o);
    if (lane == 0) red[warp] = s;
    __syncthreads();
    if (tid < 8) {
        float t = red[tid];
        #pragma unroll
        for (int o = 4; o > 0; o >>= 1) t += __shfl_xor_sync(0xffu, t, o);
        if (tid == 0) bcast = t;
    }
    __syncthreads();
    const float mean = bcast * (1.0f / DD);
    __syncthreads();

    float dx0 = v.x - mean, dx1 = v.y - mean, dx2 = v.z - mean, dx3 = v.w - mean;
    float sq = dx0*dx0 + dx1*dx1 + dx2*dx2 + dx3*dx3;
    #pragma unroll
    for (int o = 16; o > 0; o >>= 1) sq += __shfl_xor_sync(0xffffffffu, sq, o);
    if (lane == 0) red[warp] = sq;
    __syncthreads();
    if (tid < 8) {
        float t = red[tid];
        #pragma unroll
        for (int o = 4; o > 0; o >>= 1) t += __shfl_xor_sync(0xffu, t, o);
        if (tid == 0) bcast = t;
    }
    __syncthreads();
    const float inv = rsqrtf(bcast * (1.0f / DD) + EPSLN);

    float4 wv = ((const float4*)w)[tid];
    float4 bv = ((const float4*)b)[tid];
    float o0 = dx0 * inv * wv.x + bv.x;
    float o1 = dx1 * inv * wv.y + bv.y;
    float o2 = dx2 * inv * wv.z + bv.z;
    float o3 = dx3 * inv * wv.w + bv.w;

    bf16 h0,h1,h2,h3,l0,l1,l2,l3;
    split2(o0,h0,l0); split2(o1,h1,l1); split2(o2,h2,l2); split2(o3,h3,l3);
    bf162* H = (bf162*)(oh + (size_t)row * DD + tid * 4);
    bf162* L = (bf162*)(ol + (size_t)row * DD + tid * 4);
    bf162 t0; t0.x = h0; t0.y = h1; H[0] = t0;
    bf162 t1; t1.x = h2; t1.y = h3; H[1] = t1;
    bf162 t2; t2.x = l0; t2.y = l1; L[0] = t2;
    bf162 t3; t3.x = l2; t3.y = l3; L[1] = t3;
}

// ---------------------------------------------------------------------------
// Concatenate QKV biases into g_bias[3072]
// ---------------------------------------------------------------------------
__global__ void concat_bias(const float* __restrict__ bq,
                            const float* __restrict__ bk,
                            const float* __restrict__ bv,
                            float* __restrict__ out)
{
    int i = blockIdx.x * blockDim.x + threadIdx.x;
    float v;
    if (i < DD) v = bq[i];
    else if (i < 2*DD) v = bk[i - DD];
    else v = bv[i - 2*DD];
    out[i] = v;
}

// ---------------------------------------------------------------------------
// Transpose + split (generic): in fp32 [R][C] at in + z*R*C
// ---------------------------------------------------------------------------
__global__ __launch_bounds__(256)
void tsplit_kernel(const float* __restrict__ in, bf16* __restrict__ oh,
                   bf16* __restrict__ ol, int R, int C)
{
    __shared__ float t[32][33];
    const int tx = threadIdx.x, ty = threadIdx.y;
    const int c0 = blockIdx.x * 32, r0 = blockIdx.y * 32, z = blockIdx.z;
    const float* src = in + (size_t)z * R * C;
    #pragma unroll
    for (int i = 0; i < 4; i++)
        t[ty + 8*i][tx] = src[(size_t)(r0 + ty + 8*i) * C + c0 + tx];
    __syncthreads();
    #pragma unroll
    for (int i = 0; i < 4; i++) {
        int c = c0 + ty + 8*i;
        float v = t[tx][ty + 8*i];
        size_t o = (size_t)(z * C + c) * R + r0 + tx;
        bf16 h, l; split2(v, h, l);
        oh[o] = h; ol[o] = l;
    }
}

// ---------------------------------------------------------------------------
// Transpose + split for QKV weights
// ---------------------------------------------------------------------------
__global__ __launch_bounds__(256)
void tsplit_qkv(const float* __restrict__ wq, const float* __restrict__ wk,
                const float* __restrict__ wv, bf16* __restrict__ oh,
                bf16* __restrict__ ol)
{
    __shared__ float t[32][33];
    const int tx = threadIdx.x, ty = threadIdx.y;
    const int c0 = blockIdx.x * 32, r0 = blockIdx.y * 32;
    const int z = blockIdx.z;
    const int which = z >> 4, h = z & 15;
    const float* src = (which == 0 ? wq : (which == 1 ? wk : wv))
                       + (size_t)h * DD * DHH;
    #pragma unroll
    for (int i = 0; i < 4; i++)
        t[ty + 8*i][tx] = src[(size_t)(r0 + ty + 8*i) * DHH + c0 + tx];
    __syncthreads();
    #pragma unroll
    for (int i = 0; i < 4; i++) {
        int c = c0 + ty + 8*i;
        float v = t[tx][ty + 8*i];
        size_t n = (size_t)which * DD + h * DHH + c;
        size_t off = n * DD + r0 + tx;
        bf16 hh, ll; split2(v, hh, ll);
        oh[off] = hh; ol[off] = ll;
    }
}

// ---------------------------------------------------------------------------
// Split-bf16 tensor-core GEMM: C[M,N] = A[M,K] @ B[K,N]
// A hi/lo bf16 row-major [M][K]; B hi/lo bf16 [N][K].
// C = Ah*Bh + Al*Bh + Ah*Bl. BM=BN=128, BK=32, 256 thr.
// 3-stage cp.async pipeline; packed 64B rows with SW64 XOR swizzle.
// Inner loop: ALL 12 ldmatrix.x4 issued up front per 16-K chunk, then
// 48 MMAs grouped by split-term (acc reuse distance 16).
// EPI: 1=bias+gelu->split  2=bias+res->fp32  3=QKV: bias+scale->split
// ---------------------------------------------------------------------------
#define EPI_BIAS_GELU  1
#define EPI_BIAS_RES   2
#define EPI_QKV        3

#define TILE_BYTES 8192            // 128 rows * 64B
#define STG_BYTES  (4*TILE_BYTES)  // Ah,Al,Bh,Bl
#define GEMM_SMEM  (3*STG_BYTES)   // 98304 B

template <int EPI>
__global__ __launch_bounds__(256, 2)
void gemm_bf16(const bf16* __restrict__ Ah, const bf16* __restrict__ Al,
               const bf16* __restrict__ Bh, const bf16* __restrict__ Bl,
               const float* __restrict__ bias, const float* __restrict__ Rm,
               float* __restrict__ Cf, bf16* __restrict__ Oh,
               bf16* __restrict__ Ol, int M, int N, int K)
{
    extern __shared__ bf16 sm[];
    const int tid = threadIdx.x;
    const int bx = blockIdx.x, by = blockIdx.y;
    const int warp = tid >> 5, lane = tid & 31;
    const int wm = warp >> 1, wn = warp & 1;

    // ---- loader mapping: row = tid/2, 32B half-row per thread ----
    const int lrow = tid >> 1;
    const int lhalf = (tid & 1);
    const bf16* gAh = Ah + (size_t)(by * 128 + lrow) * K + lhalf * 16;
    const bf16* gAl = Al + (size_t)(by * 128 + lrow) * K + lhalf * 16;
    const bf16* gBh = Bh + (size_t)(bx * 128 + lrow) * K + lhalf * 16;
    const bf16* gBl = Bl + (size_t)(bx * 128 + lrow) * K + lhalf * 16;
    const uint32_t sbase = cvta_s(sm);
    const uint32_t lxm = (uint32_t)((lrow & 6) << 3);
    const uint32_t lso0 = lrow * 64 + ((lhalf * 32)      ^ lxm);
    const uint32_t lso1 = lrow * 64 + ((lhalf * 32 + 16) ^ lxm);

    float acc[2][8][4];
    #pragma unroll
    for (int i = 0; i < 2; i++)
        #pragma unroll
        for (int j = 0; j < 8; j++)
            #pragma unroll
            for (int q = 0; q < 4; q++) acc[i][j][q] = 0.0f;

    // ---- ldmatrix lane decodes (element indices) ----
    const int a_r = (lane & 7) + ((lane >> 3) & 1) * 8;
    const int a_c = (lane >> 4) * 8;
    const int b_r = (lane & 7) + (lane >> 4) * 8;
    const int b_c = ((lane >> 3) & 1) * 8;

    uint32_t arow[2], axm[2];
    #pragma unroll
    for (int mf = 0; mf < 2; mf++) {
        int r = wm*32 + mf*16 + a_r;
        arow[mf] = (uint32_t)r * 64;
        axm[mf]  = (uint32_t)((r & 6) << 3);
    }
    uint32_t brow[4], bxm[4];
    #pragma unroll
    for (int p = 0; p < 4; p++) {
        int r = wn*64 + p*16 + b_r;
        brow[p] = (uint32_t)r * 64;
        bxm[p]  = (uint32_t)((r & 6) << 3);
    }
    const uint32_t acb = (uint32_t)(a_c * 2);
    const uint32_t bcb = (uint32_t)(b_c * 2);

    const int T = K / 32;

    auto issue = [&](int s, int kk) {
        uint32_t st = sbase + (uint32_t)s * STG_BYTES;
        cp16(st + lso0,                gAh + kk);
        cp16(st + lso1,                gAh + kk + 8);
        cp16(st + TILE_BYTES   + lso0, gAl + kk);
        cp16(st + TILE_BYTES   + lso1, gAl + kk + 8);
        cp16(st + TILE_BYTES*2 + lso0, gBh + kk);
        cp16(st + TILE_BYTES*2 + lso1, gBh + kk + 8);
        cp16(st + TILE_BYTES*3 + lso0, gBl + kk);
        cp16(st + TILE_BYTES*3 + lso1, gBl + kk + 8);
        asm volatile("cp.async.commit_group;");
    };

    issue(0, 0);
    if (T > 1) issue(1, 32);

    int stage = 0;
    for (int t = 0; t < T; t++) {
        if (t + 2 < T) {
            issue((stage + 2) % 3, (t + 2) * 32);
            asm volatile("cp.async.wait_group 2;");
        } else if (t + 1 < T) {
            asm volatile("cp.async.wait_group 1;");
        } else {
            asm volatile("cp.async.wait_group 0;");
        }
        __syncthreads();

        const uint32_t st  = sbase + (uint32_t)stage * STG_BYTES;
        const uint32_t sAh = st;
        const uint32_t sAl = st + TILE_BYTES;
        const uint32_t sBh = st + TILE_BYTES*2;
        const uint32_t sBl = st + TILE_BYTES*3;

        #pragma unroll
        for (int kc = 0; kc < 2; kc++) {
            const uint32_t kb = (uint32_t)(kc * 32);

            // ---- issue ALL fragment loads up front (12 x ldmatrix.x4) ----
            unsigned ah[2][4], al[2][4];
            #pragma unroll
            for (int mf = 0; mf < 2; mf++) {
                uint32_t ao = arow[mf] + ((kb + acb) ^ axm[mf]);
                ldsm4(ah[mf], sAh + ao);
                ldsm4(al[mf], sAl + ao);
            }
            unsigned bh4[4][4], bl4[4][4];
            #pragma unroll
            for (int p = 0; p < 4; p++) {
                uint32_t bo = brow[p] + ((kb + bcb) ^ bxm[p]);
                ldsm4(bh4[p], sBh + bo);
                ldsm4(bl4[p], sBl + bo);
            }

            // ---- 48 MMAs in 3 term-grouped bursts ----
            #pragma unroll
            for (int p = 0; p < 4; p++)
                #pragma unroll
                for (int mf = 0; mf < 2; mf++) {
                    mma16816(acc[mf][2*p],     ah[mf], bh4[p]);
                    mma16816(acc[mf][2*p + 1], ah[mf], bh4[p] + 2);
                }
            #pragma unroll
            for (int p = 0; p < 4; p++)
                #pragma unroll
                for (int mf = 0; mf < 2; mf++) {
                    mma16816(acc[mf][2*p],     al[mf], bh4[p]);
                    mma16816(acc[mf][2*p + 1], al[mf], bh4[p] + 2);
                }
            #pragma unroll
            for (int p = 0; p < 4; p++)
                #pragma unroll
                for (int mf = 0; mf < 2; mf++) {
                    mma16816(acc[mf][2*p],     ah[mf], bl4[p]);
                    mma16816(acc[mf][2*p + 1], ah[mf], bl4[p] + 2);
                }
        }
        __syncthreads();
        stage = (stage + 1) % 3;
    }

    const int er = by * 128 + wm * 32 + (lane >> 2);
    const int ec = bx * 128 + wn * 64 + (lane & 3) * 2;
    #pragma unroll
    for (int mf = 0; mf < 2; mf++) {
        #pragma unroll
        for (int nf = 0; nf < 8; nf++) {
            int c = ec + nf * 8;
            float b0 = bias[c], b1 = bias[c + 1];
            #pragma unroll
            for (int half = 0; half < 2; half++) {
                int r = er + mf * 16 + half * 8;
                float v0 = acc[mf][nf][half * 2 + 0] + b0;
                float v1 = acc[mf][nf][half * 2 + 1] + b1;
                if (EPI == EPI_BIAS_GELU || EPI == EPI_QKV) {
                    if (EPI == EPI_BIAS_GELU) {
                        v0 = gelu_exact(v0); v1 = gelu_exact(v1);
                    } else {
                        float sc = (c < DD) ? 0.125f : 1.0f;
                        v0 *= sc; v1 *= sc;
                    }
                    bf16 h0,h1,l0,l1;
                    split2(v0,h0,l0); split2(v1,h1,l1);
                    bf162 th; th.x = h0; th.y = h1;
                    bf162 tl; tl.x = l0; tl.y = l1;
                    *(bf162*)(Oh + (size_t)r * N + c) = th;
                    *(bf162*)(Ol + (size_t)r * N + c) = tl;
                } else {
                    float2 rr = *(const float2*)(Rm + (size_t)r * N + c);
                    v0 += rr.x; v1 += rr.y;
                    float2 o; o.x = v0; o.y = v1;
                    *(float2*)(Cf + (size_t)r * N + c) = o;
                }
            }
        }
    }
}

// ---------------------------------------------------------------------------
// Tensor-core flash attention with split-bf16 precision (unchanged).
// ---------------------------------------------------------------------------
#define AQS   72
#define ATILE (64*AQS)
#define ATTN_SMEM ((2*ATILE + 8*ATILE) * 2)

__global__ __launch_bounds__(128, 2)
void attn_mma(const bf16* __restrict__ qkvh, const bf16* __restrict__ qkvl,
              bf16* __restrict__ zh, bf16* __restrict__ zl)
{
    extern __shared__ bf16 smb[];
    const uint32_t sbase = cvta_s(smb);
    const int tid  = threadIdx.x;
    const int warp = tid >> 5, lane = tid & 31;
    const int qt = blockIdx.x;
    const int bh = blockIdx.y;
    const int h  = bh & 15;
    const int hcol = h * DHH;
    const int tokbase = (bh >> 4) * SS;

    const uint32_t oQh = 0, oQl = ATILE;
    auto stageoff = [](int s) { return (uint32_t)(2*ATILE + s*4*ATILE); };

    const int ldrow = tid >> 1;
    const int ldc0  = (tid & 1) * 32;
    auto ld_tensor = [&](uint32_t selems, const bf16* g, int tok0, int coff) {
        const bf16* gp = g + (size_t)(tok0 + ldrow) * (3*DD) + coff + ldc0;
        uint32_t sp = sbase + (selems + ldrow * AQS + ldc0) * 2;
        cp16(sp,      gp);
        cp16(sp + 16, gp + 8);
        cp16(sp + 32, gp + 16);
        cp16(sp + 48, gp + 24);
    };
    auto issue_kv = [&](int s, int kt) {
        int tok0 = tokbase + kt * 64;
        uint32_t so = stageoff(s);
        ld_tensor(so,           qkvh, tok0, DD   + hcol);
        ld_tensor(so + ATILE,   qkvl, tok0, DD   + hcol);
        ld_tensor(so + 2*ATILE, qkvh, tok0, 2*DD + hcol);
        ld_tensor(so + 3*ATILE, qkvl, tok0, 2*DD + hcol);
        asm volatile("cp.async.commit_group;");
    };

    {
        int tok0 = tokbase + qt * 64;
        ld_tensor(oQh, qkvh, tok0, hcol);
        ld_tensor(oQl, qkvl, tok0, hcol);
        issue_kv(0, 0);
    }

    const int a_r  = (lane & 7) + ((lane >> 3) & 1) * 8;
    const int a_c  = (lane >> 4) * 8;
    const int kb_r = (lane & 7) + (lane >> 4) * 8;
    const int kb_c = ((lane >> 3) & 1) * 8;
    const int vb_r = (lane & 7) + ((lane >> 3) & 1) * 8;
    const int vb_c = (lane >> 4) * 8;

    unsigned qh[4][4], ql[4][4];
    float o[8][4];
    #pragma unroll
    for (int j = 0; j < 8; j++)
        #pragma unroll
        for (int q = 0; q < 4; q++) o[j][q] = 0.0f;
    float m0 = -INFINITY, m1 = -INFINITY, l0 = 0.0f, l1 = 0.0f;

    const int r0 = lane >> 2;
    const int colq = 2 * (lane & 3);

    for (int kt = 0; kt <= qt; kt++) {
        if (kt + 1 <= qt) {
            issue_kv((kt + 1) & 1, kt + 1);
            asm volatile("cp.async.wait_group 1;");
        } else {
            asm volatile("cp.async.wait_group 0;");
        }
        __syncthreads();

        if (kt == 0) {
            #pragma unroll
            for (int kc = 0; kc < 4; kc++) {
                uint32_t ao = ((warp*16 + a_r) * AQS + kc*16 + a_c) * 2;
                ldsm4(qh[kc], sbase + (oQh)*2 + ao);
                ldsm4(ql[kc], sbase + (oQl)*2 + ao);
            }
        }

        const uint32_t so = stageoff(kt & 1);
        const uint32_t sKh = sbase + so * 2;
        const uint32_t sKl = sbase + (so + ATILE) * 2;
        const uint32_t sVh = sbase + (so + 2*ATILE) * 2;
        const uint32_t sVl = sbase + (so + 3*ATILE) * 2;

        float s[8][4];
        #pragma unroll
        for (int j = 0; j < 8; j++)
            #pragma unroll
            for (int q = 0; q < 4; q++) s[j][q] = 0.0f;

        #pragma unroll
        for (int jp = 0; jp < 4; jp++) {
            #pragma unroll
            for (int kc = 0; kc < 4; kc++) {
                unsigned kh4[4], kl4[4];
                uint32_t ko = ((jp*16 + kb_r) * AQS + kc*16 + kb_c) * 2;
                ldsm4(kh4, sKh + ko);
                ldsm4(kl4, sKl + ko);
                mma16816(s[2*jp],   qh[kc], kh4);
                mma16816(s[2*jp+1], qh[kc], kh4 + 2);
                mma16816(s[2*jp],   ql[kc], kh4);
                mma16816(s[2*jp+1], ql[kc], kh4 + 2);
                mma16816(s[2*jp],   qh[kc], kl4);
                mma16816(s[2*jp+1], qh[kc], kl4 + 2);
            }
        }

        if (kt == qt) {
            const int rg0 = warp*16 + r0;
            #pragma unroll
            for (int j = 0; j < 8; j++) {
                int cg = j*8 + colq;
                if (cg     > rg0) s[j][0] = -1e30f;
                if (cg + 1 > rg0) s[j][1] = -1e30f;
                if (cg     > rg0 + 8) s[j][2] = -1e30f;
                if (cg + 1 > rg0 + 8) s[j][3] = -1e30f;
            }
        }

        float vmax0 = -INFINITY, vmax1 = -INFINITY;
        #pragma unroll
        for (int j = 0; j < 8; j++) {
            vmax0 = fmaxf(vmax0, fmaxf(s[j][0], s[j][1]));
            vmax1 = fmaxf(vmax1, fmaxf(s[j][2], s[j][3]));
        }
        vmax0 = fmaxf(vmax0, __shfl_xor_sync(0xffffffffu, vmax0, 1));
        vmax0 = fmaxf(vmax0, __shfl_xor_sync(0xffffffffu, vmax0, 2));
        vmax1 = fmaxf(vmax1, __shfl_xor_sync(0xffffffffu, vmax1, 1));
        vmax1 = fmaxf(vmax1, __shfl_xor_sync(0xffffffffu, vmax1, 2));

        float mn0 = fmaxf(m0, vmax0), mn1 = fmaxf(m1, vmax1);
        float f0 = __expf(m0 - mn0), f1 = __expf(m1 - mn1);
        m0 = mn0; m1 = mn1;

        float rs0 = 0.0f, rs1 = 0.0f;
        #pragma unroll
        for (int j = 0; j < 8; j++) {
            s[j][0] = __expf(s[j][0] - mn0);
            s[j][1] = __expf(s[j][1] - mn0);
            s[j][2] = __expf(s[j][2] - mn1);
            s[j][3] = __expf(s[j][3] - mn1);
            rs0 += s[j][0] + s[j][1];
            rs1 += s[j][2] + s[j][3];
        }
        rs0 += __shfl_xor_sync(0xffffffffu, rs0, 1);
        rs0 += __shfl_xor_sync(0xffffffffu, rs0, 2);
        rs1 += __shfl_xor_sync(0xffffffffu, rs1, 1);
        rs1 += __shfl_xor_sync(0xffffffffu, rs1, 2);
        l0 = l0 * f0 + rs0;
        l1 = l1 * f1 + rs1;

        #pragma unroll
        for (int j = 0; j < 8; j++) {
            o[j][0] *= f0; o[j][1] *= f0;
            o[j][2] *= f1; o[j][3] *= f1;
        }

        unsigned ph[4][4], pl[4][4];
        #pragma unroll
        for (int jc = 0; jc < 4; jc++) {
            const int j0 = 2*jc, j1 = 2*jc + 1;
            #define SPLITPAIR(a, b, HI, LOI)                       \
                {  bf16 _h0,_l0,_h1,_l1;                           \
                   split2(a,_h0,_l0); split2(b,_h1,_l1);           \
                   HI  = packbf(__bfloat162float(_h0), __bfloat162float(_h1)); \
                   LOI = packbf(__bfloat162float(_l0), __bfloat162float(_l1)); }
            SPLITPAIR(s[j0][0], s[j0][1], ph[jc][0], pl[jc][0]);
            SPLITPAIR(s[j0][2], s[j0][3], ph[jc][1], pl[jc][1]);
            SPLITPAIR(s[j1][0], s[j1][1], ph[jc][2], pl[jc][2]);
            SPLITPAIR(s[j1][2], s[j1][3], ph[jc][3], pl[jc][3]);
            #undef SPLITPAIR
        }

        #pragma unroll
        for (int jc = 0; jc < 4; jc++) {
            #pragma unroll
            for (int np = 0; np < 4; np++) {
                unsigned vh4[4], vl4[4];
                uint32_t vo = ((jc*16 + vb_r) * AQS + np*16 + vb_c) * 2;
                ldsm4t(vh4, sVh + vo);
                ldsm4t(vl4, sVl + vo);
                mma16816(o[2*np],   ph[jc], vh4);
                mma16816(o[2*np+1], ph[jc], vh4 + 2);
                mma16816(o[2*np],   pl[jc], vh4);
                mma16816(o[2*np+1], pl[jc], vh4 + 2);
                mma16816(o[2*np],   ph[jc], vl4);
                mma16816(o[2*np+1], ph[jc], vl4 + 2);
            }
        }
        __syncthreads();
    }

    const float il0 = 1.0f / l0, il1 = 1.0f / l1;
    const int row0 = tokbase + qt*64 + warp*16 + r0;
    #pragma unroll
    for (int j = 0; j < 8; j++) {
        int c = hcol + j*8 + colq;
        float a0 = o[j][0] * il0, a1 = o[j][1] * il0;
        float b0 = o[j][2] * il1, b1 = o[j][3] * il1;
        bf16 h0,lo0,h1,lo1;
        split2(a0,h0,lo0); split2(a1,h1,lo1);
        bf162 th; th.x = h0; th.y = h1;
        bf162 tl; tl.x = lo0; tl.y = lo1;
        *(bf162*)(zh + (size_t)row0 * DD + c) = th;
        *(bf162*)(zl + (size_t)row0 * DD + c) = tl;
        split2(b0,h0,lo0); split2(b1,h1,lo1);
        th.x = h0; th.y = h1;
        tl.x = lo0; tl.y = lo1;
        *(bf162*)(zh + (size_t)(row0 + 8) * DD + c) = th;
        *(bf162*)(zl + (size_t)(row0 + 8) * DD + c) = tl;
    }
}

// ---------------------------------------------------------------------------
// Host launcher
// ---------------------------------------------------------------------------
extern "C" void kernel_launch(void* const* d_in, const int* in_sizes, int n_in,
                              void* d_out, int out_size)
{
    (void)in_sizes; (void)n_in; (void)out_size;
    const float* resid = (const float*)d_in[0];
    const float* ln1w  = (const float*)d_in[1];
    const float* ln1b  = (const float*)d_in[2];
    const float* WQ    = (const float*)d_in[3];
    const float* bQ    = (const float*)d_in[4];
    const float* WK    = (const float*)d_in[5];
    const float* bK    = (const float*)d_in[6];
    const float* WV    = (const float*)d_in[7];
    const float* bV    = (const float*)d_in[8];
    const float* WO    = (const float*)d_in[9];
    const float* bO    = (const float*)d_in[10];
    const float* ln2w  = (const float*)d_in[11];
    const float* ln2b  = (const float*)d_in[12];
    const float* Win   = (const float*)d_in[13];
    const float* bin   = (const float*)d_in[14];
    const float* Wout  = (const float*)d_in[15];
    const float* bout  = (const float*)d_in[16];

    float *mid, *biasqkv;
    bf16 *xh, *xl, *qkvh, *qkvl, *acth, *actl, *wh, *wl;
    cudaGetSymbolAddress((void**)&mid,   g_mid);
    cudaGetSymbolAddress((void**)&biasqkv, g_bias);
    cudaGetSymbolAddress((void**)&xh,    g_xh);
    cudaGetSymbolAddress((void**)&xl,    g_xl);
    cudaGetSymbolAddress((void**)&qkvh,  g_qkvh);
    cudaGetSymbolAddress((void**)&qkvl,  g_qkvl);
    cudaGetSymbolAddress((void**)&acth,  g_acth);
    cudaGetSymbolAddress((void**)&actl,  g_actl);
    cudaGetSymbolAddress((void**)&wh,    g_wh);
    cudaGetSymbolAddress((void**)&wl,    g_wl);

    cudaFuncSetAttribute(attn_mma, cudaFuncAttributeMaxDynamicSharedMemorySize,
                         ATTN_SMEM);
    cudaFuncSetAttribute(gemm_bf16<EPI_QKV>,
                         cudaFuncAttributeMaxDynamicSharedMemorySize, GEMM_SMEM);
    cudaFuncSetAttribute(gemm_bf16<EPI_BIAS_GELU>,
                         cudaFuncAttributeMaxDynamicSharedMemorySize, GEMM_SMEM);
    cudaFuncSetAttribute(gemm_bf16<EPI_BIAS_RES>,
                         cudaFuncAttributeMaxDynamicSharedMemorySize, GEMM_SMEM);

    dim3 tb(32, 8);

    // 1) LN1 -> split
    ln_split_kernel<<<NTOK, 256>>>(resid, ln1w, ln1b, xh, xl);

    // 2) fused QKV
    concat_bias<<<12, 256>>>(bQ, bK, bV, biasqkv);
    tsplit_qkv<<<dim3(DHH/32, DD/32, 48), tb>>>(WQ, WK, WV, wh, wl);
    dim3 g3072(3*DD/128, NTOK/128);
    gemm_bf16<EPI_QKV><<<g3072, 256, GEMM_SMEM>>>(xh, xl, wh, wl, biasqkv,
                                                  nullptr, nullptr, qkvh, qkvl,
                                                  NTOK, 3*DD, DD);

    // 3) tensor-core causal attention -> z split (into xh/xl)
    dim3 ga(SS / 64, BB * HH);
    attn_mma<<<ga, 128, ATTN_SMEM>>>(qkvh, qkvl, xh, xl);

    // 4) O-projection + residual -> mid
    dim3 g1024(DD/128, NTOK/128);
    tsplit_kernel<<<dim3(DD/32, DD/32, 1), tb>>>(WO, wh, wl, DD, DD);
    gemm_bf16<EPI_BIAS_RES><<<g1024, 256, GEMM_SMEM>>>(xh, xl, wh, wl, bO, resid,
                                                       mid, nullptr, nullptr,
                                                       NTOK, DD, DD);

    // 5) LN2 -> split
    ln_split_kernel<<<NTOK, 256>>>(mid, ln2w, ln2b, xh, xl);

    // 6) MLP in + exact GELU -> split act
    dim3 g4096(DMM/128, NTOK/128);
    tsplit_kernel<<<dim3(DMM/32, DD/32, 1), tb>>>(Win, wh, wl, DD, DMM);
    gemm_bf16<EPI_BIAS_GELU><<<g4096, 256, GEMM_SMEM>>>(xh, xl, wh, wl, bin,
                                                        nullptr, nullptr,
                                                        acth, actl,
                                                        NTOK, DMM, DD);

    // 7) MLP out + bias + residual -> d_out
    tsplit_kernel<<<dim3(DD/32, DMM/32, 1), tb>>>(Wout, wh, wl, DMM, DD);
    gemm_bf16<EPI_BIAS_RES><<<g1024, 256, GEMM_SMEM>>>(acth, actl, wh, wl, bout,
                                                       mid, (float*)d_out,
                                                       nullptr, nullptr,
                                                       NTOK, DD, DMM);
}

// round 12
// speedup vs baseline: 1.2202x; 1.2202x over previous
#include <cuda_runtime.h>
#include <cuda_bf16.h>
#include <cuda_fp16.h>
#include <math.h>
#include <stdint.h>

// Problem constants
#define BB   2
#define SS   2048
#define DD   1024
#define HH   16
#define DHH  64
#define DMM  4096
#define NTOK (BB*SS)          // 4096
#define EPSLN 1e-5f

typedef __nv_bfloat16  bf16;
typedef __nv_bfloat162 bf162;

// ---------------------------------------------------------------------------
// Device scratch (half reuses the 2-byte bf16 buffers by cast)
// ---------------------------------------------------------------------------
__device__ float g_mid[NTOK*DD];
__device__ float g_bias[3*DD];        // concatenated QKV bias
__device__ bf16  g_xh [NTOK*DD];      // split activations hi (bf16 or fp16 phase)
__device__ bf16  g_xl [NTOK*DD];      // split activations lo
__device__ bf16  g_qkvh[NTOK*3*DD];   // fused QKV output (hi)
__device__ bf16  g_qkvl[NTOK*3*DD];   // fused QKV output (lo)
__device__ bf16  g_acth[NTOK*DMM];    // gelu output split (hi, fp16)
__device__ bf16  g_actl[NTOK*DMM];    // gelu output split (lo, fp16)
__device__ bf16  g_wh [DD*DMM];       // split/single transposed weight (hi)
__device__ bf16  g_wl [DD*DMM];       // split transposed weight (lo)

// ---------------------------------------------------------------------------
// Helpers
// ---------------------------------------------------------------------------
__device__ __forceinline__ void split2(float x, bf16& h, bf16& l)
{
    h = __float2bfloat16_rn(x);
    l = __float2bfloat16_rn(x - __bfloat162float(h));
}

__device__ __forceinline__ void split2h(float x, __half& h, __half& l)
{
    h = __float2half_rn(x);
    l = __float2half_rn(x - __half2float(h));
}

__device__ __forceinline__ uint32_t cvta_s(const void* p)
{
    return (uint32_t)__cvta_generic_to_shared(p);
}

__device__ __forceinline__ void cp16(uint32_t s, const void* g)
{
    asm volatile("cp.async.cg.shared.global [%0], [%1], 16;" :: "r"(s), "l"(g));
}

__device__ __forceinline__ void ldsm4(unsigned r[4], uint32_t a)
{
    asm volatile("ldmatrix.sync.aligned.m8n8.x4.shared.b16 {%0,%1,%2,%3}, [%4];"
                 : "=r"(r[0]), "=r"(r[1]), "=r"(r[2]), "=r"(r[3]) : "r"(a));
}

__device__ __forceinline__ void ldsm4t(unsigned r[4], uint32_t a)
{
    asm volatile("ldmatrix.sync.aligned.m8n8.x4.trans.shared.b16 {%0,%1,%2,%3}, [%4];"
                 : "=r"(r[0]), "=r"(r[1]), "=r"(r[2]), "=r"(r[3]) : "r"(a));
}

__device__ __forceinline__ void mma16816(float c[4], const unsigned a[4],
                                         const unsigned b[2])
{
    asm volatile(
        "mma.sync.aligned.m16n8k16.row.col.f32.bf16.bf16.f32 "
        "{%0,%1,%2,%3}, {%4,%5,%6,%7}, {%8,%9}, {%0,%1,%2,%3};"
        : "+f"(c[0]), "+f"(c[1]), "+f"(c[2]), "+f"(c[3])
        : "r"(a[0]), "r"(a[1]), "r"(a[2]), "r"(a[3]), "r"(b[0]), "r"(b[1]));
}

__device__ __forceinline__ void mma16816h(float c[4], const unsigned a[4],
                                          const unsigned b[2])
{
    asm volatile(
        "mma.sync.aligned.m16n8k16.row.col.f32.f16.f16.f32 "
        "{%0,%1,%2,%3}, {%4,%5,%6,%7}, {%8,%9}, {%0,%1,%2,%3};"
        : "+f"(c[0]), "+f"(c[1]), "+f"(c[2]), "+f"(c[3])
        : "r"(a[0]), "r"(a[1]), "r"(a[2]), "r"(a[3]), "r"(b[0]), "r"(b[1]));
}

__device__ __forceinline__ unsigned packbf(float a, float b)
{
    bf162 t = __floats2bfloat162_rn(a, b);
    return *reinterpret_cast<unsigned*>(&t);
}

__device__ __forceinline__ float gelu_exact(float x)
{
    return 0.5f * x * (1.0f + erff(x * 0.70710678118654752f));
}

// ---------------------------------------------------------------------------
// LayerNorm + split. OUT16=0: bf16 hi/lo.  OUT16=1: fp16 hi/lo.
// ---------------------------------------------------------------------------
template <int OUT16>
__global__ __launch_bounds__(256)
void ln_split_kernel(const float* __restrict__ x, const float* __restrict__ w,
                     const float* __restrict__ b, void* __restrict__ oh_,
                     void* __restrict__ ol_)
{
    __shared__ float red[8];
    __shared__ float bcast;
    const int row = blockIdx.x;
    const int tid = threadIdx.x;
    const int lane = tid & 31, warp = tid >> 5;

    float4 v = ((const float4*)(x + (size_t)row * DD))[tid];

    float s = v.x + v.y + v.z + v.w;
    #pragma unroll
    for (int o = 16; o > 0; o >>= 1) s += __shfl_xor_sync(0xffffffffu, s, o);
    if (lane == 0) red[warp] = s;
    __syncthreads();
    if (tid < 8) {
        float t = red[tid];
        #pragma unroll
        for (int o = 4; o > 0; o >>= 1) t += __shfl_xor_sync(0xffu, t, o);
        if (tid == 0) bcast = t;
    }
    __syncthreads();
    const float mean = bcast * (1.0f / DD);
    __syncthreads();

    float dx0 = v.x - mean, dx1 = v.y - mean, dx2 = v.z - mean, dx3 = v.w - mean;
    float sq = dx0*dx0 + dx1*dx1 + dx2*dx2 + dx3*dx3;
    #pragma unroll
    for (int o = 16; o > 0; o >>= 1) sq += __shfl_xor_sync(0xffffffffu, sq, o);
    if (lane == 0) red[warp] = sq;
    __syncthreads();
    if (tid < 8) {
        float t = red[tid];
        #pragma unroll
        for (int o = 4; o > 0; o >>= 1) t += __shfl_xor_sync(0xffu, t, o);
        if (tid == 0) bcast = t;
    }
    __syncthreads();
    const float inv = rsqrtf(bcast * (1.0f / DD) + EPSLN);

    float4 wv = ((const float4*)w)[tid];
    float4 bv = ((const float4*)b)[tid];
    float o0 = dx0 * inv * wv.x + bv.x;
    float o1 = dx1 * inv * wv.y + bv.y;
    float o2 = dx2 * inv * wv.z + bv.z;
    float o3 = dx3 * inv * wv.w + bv.w;

    if (OUT16) {
        __half h0,h1,h2,h3,l0,l1,l2,l3;
        split2h(o0,h0,l0); split2h(o1,h1,l1); split2h(o2,h2,l2); split2h(o3,h3,l3);
        __half2* H = (__half2*)((__half*)oh_ + (size_t)row * DD + tid * 4);
        __half2* L = (__half2*)((__half*)ol_ + (size_t)row * DD + tid * 4);
        H[0] = __halves2half2(h0, h1); H[1] = __halves2half2(h2, h3);
        L[0] = __halves2half2(l0, l1); L[1] = __halves2half2(l2, l3);
    } else {
        bf16 h0,h1,h2,h3,l0,l1,l2,l3;
        split2(o0,h0,l0); split2(o1,h1,l1); split2(o2,h2,l2); split2(o3,h3,l3);
        bf162* H = (bf162*)((bf16*)oh_ + (size_t)row * DD + tid * 4);
        bf162* L = (bf162*)((bf16*)ol_ + (size_t)row * DD + tid * 4);
        bf162 t0; t0.x = h0; t0.y = h1; H[0] = t0;
        bf162 t1; t1.x = h2; t1.y = h3; H[1] = t1;
        bf162 t2; t2.x = l0; t2.y = l1; L[0] = t2;
        bf162 t3; t3.x = l2; t3.y = l3; L[1] = t3;
    }
}

// ---------------------------------------------------------------------------
// Concatenate QKV biases into g_bias[3072]
// ---------------------------------------------------------------------------
__global__ void concat_bias(const float* __restrict__ bq,
                            const float* __restrict__ bk,
                            const float* __restrict__ bv,
                            float* __restrict__ out)
{
    int i = blockIdx.x * blockDim.x + threadIdx.x;
    float v;
    if (i < DD) v = bq[i];
    else if (i < 2*DD) v = bk[i - DD];
    else v = bv[i - 2*DD];
    out[i] = v;
}

// ---------------------------------------------------------------------------
// Transpose + single-fp16 convert: out16[(c)*R + r] = fp16(in[r][c])
// ---------------------------------------------------------------------------
__global__ __launch_bounds__(256)
void tsplit16_kernel(const float* __restrict__ in, __half* __restrict__ o16,
                     int R, int C)
{
    __shared__ float t[32][33];
    const int tx = threadIdx.x, ty = threadIdx.y;
    const int c0 = blockIdx.x * 32, r0 = blockIdx.y * 32;
    #pragma unroll
    for (int i = 0; i < 4; i++)
        t[ty + 8*i][tx] = in[(size_t)(r0 + ty + 8*i) * C + c0 + tx];
    __syncthreads();
    #pragma unroll
    for (int i = 0; i < 4; i++) {
        int c = c0 + ty + 8*i;
        o16[(size_t)c * R + r0 + tx] = __float2half_rn(t[tx][ty + 8*i]);
    }
}

// ---------------------------------------------------------------------------
// Transpose + split for QKV weights (bf16 hi/lo, unchanged)
// ---------------------------------------------------------------------------
__global__ __launch_bounds__(256)
void tsplit_qkv(const float* __restrict__ wq, const float* __restrict__ wk,
                const float* __restrict__ wv, bf16* __restrict__ oh,
                bf16* __restrict__ ol)
{
    __shared__ float t[32][33];
    const int tx = threadIdx.x, ty = threadIdx.y;
    const int c0 = blockIdx.x * 32, r0 = blockIdx.y * 32;
    const int z = blockIdx.z;
    const int which = z >> 4, h = z & 15;
    const float* src = (which == 0 ? wq : (which == 1 ? wk : wv))
                       + (size_t)h * DD * DHH;
    #pragma unroll
    for (int i = 0; i < 4; i++)
        t[ty + 8*i][tx] = src[(size_t)(r0 + ty + 8*i) * DHH + c0 + tx];
    __syncthreads();
    #pragma unroll
    for (int i = 0; i < 4; i++) {
        int c = c0 + ty + 8*i;
        float v = t[tx][ty + 8*i];
        size_t n = (size_t)which * DD + h * DHH + c;
        size_t off = n * DD + r0 + tx;
        bf16 hh, ll; split2(v, hh, ll);
        oh[off] = hh; ol[off] = ll;
    }
}

// ---------------------------------------------------------------------------
// 3-term split-bf16 HMMA GEMM (QKV only).  EPI fixed: bias+scale -> split bf16
// ---------------------------------------------------------------------------
#define TILE_BYTES 8192            // 128 rows * 64B
#define STG_BYTES  (4*TILE_BYTES)
#define GEMM_SMEM  (3*STG_BYTES)   // 98304 B

__global__ __launch_bounds__(256, 2)
void gemm_bf16_qkv(const bf16* __restrict__ Ah, const bf16* __restrict__ Al,
                   const bf16* __restrict__ Bh, const bf16* __restrict__ Bl,
                   const float* __restrict__ bias,
                   bf16* __restrict__ Oh, bf16* __restrict__ Ol,
                   int M, int N, int K)
{
    extern __shared__ bf16 sm[];
    const int tid = threadIdx.x;
    const int bx = blockIdx.x, by = blockIdx.y;
    const int warp = tid >> 5, lane = tid & 31;
    const int wm = warp >> 1, wn = warp & 1;

    const int lrow = tid >> 1;
    const int lhalf = (tid & 1);
    const bf16* gAh = Ah + (size_t)(by * 128 + lrow) * K + lhalf * 16;
    const bf16* gAl = Al + (size_t)(by * 128 + lrow) * K + lhalf * 16;
    const bf16* gBh = Bh + (size_t)(bx * 128 + lrow) * K + lhalf * 16;
    const bf16* gBl = Bl + (size_t)(bx * 128 + lrow) * K + lhalf * 16;
    const uint32_t sbase = cvta_s(sm);
    const uint32_t lxm = (uint32_t)((lrow & 6) << 3);
    const uint32_t lso0 = lrow * 64 + ((lhalf * 32)      ^ lxm);
    const uint32_t lso1 = lrow * 64 + ((lhalf * 32 + 16) ^ lxm);

    float acc[2][8][4];
    #pragma unroll
    for (int i = 0; i < 2; i++)
        #pragma unroll
        for (int j = 0; j < 8; j++)
            #pragma unroll
            for (int q = 0; q < 4; q++) acc[i][j][q] = 0.0f;

    const int a_r = (lane & 7) + ((lane >> 3) & 1) * 8;
    const int a_c = (lane >> 4) * 8;
    const int b_r = (lane & 7) + (lane >> 4) * 8;
    const int b_c = ((lane >> 3) & 1) * 8;

    uint32_t arow[2], axm[2];
    #pragma unroll
    for (int mf = 0; mf < 2; mf++) {
        int r = wm*32 + mf*16 + a_r;
        arow[mf] = (uint32_t)r * 64;
        axm[mf]  = (uint32_t)((r & 6) << 3);
    }
    uint32_t brow[4], bxm[4];
    #pragma unroll
    for (int p = 0; p < 4; p++) {
        int r = wn*64 + p*16 + b_r;
        brow[p] = (uint32_t)r * 64;
        bxm[p]  = (uint32_t)((r & 6) << 3);
    }
    const uint32_t acb = (uint32_t)(a_c * 2);
    const uint32_t bcb = (uint32_t)(b_c * 2);

    const int T = K / 32;

    auto issue = [&](int s, int kk) {
        uint32_t st = sbase + (uint32_t)s * STG_BYTES;
        cp16(st + lso0,                gAh + kk);
        cp16(st + lso1,                gAh + kk + 8);
        cp16(st + TILE_BYTES   + lso0, gAl + kk);
        cp16(st + TILE_BYTES   + lso1, gAl + kk + 8);
        cp16(st + TILE_BYTES*2 + lso0, gBh + kk);
        cp16(st + TILE_BYTES*2 + lso1, gBh + kk + 8);
        cp16(st + TILE_BYTES*3 + lso0, gBl + kk);
        cp16(st + TILE_BYTES*3 + lso1, gBl + kk + 8);
        asm volatile("cp.async.commit_group;");
    };

    issue(0, 0);
    if (T > 1) issue(1, 32);

    int stage = 0;
    for (int t = 0; t < T; t++) {
        if (t + 2 < T) {
            issue((stage + 2) % 3, (t + 2) * 32);
            asm volatile("cp.async.wait_group 2;");
        } else if (t + 1 < T) {
            asm volatile("cp.async.wait_group 1;");
        } else {
            asm volatile("cp.async.wait_group 0;");
        }
        __syncthreads();

        const uint32_t st  = sbase + (uint32_t)stage * STG_BYTES;
        const uint32_t sAh = st;
        const uint32_t sAl = st + TILE_BYTES;
        const uint32_t sBh = st + TILE_BYTES*2;
        const uint32_t sBl = st + TILE_BYTES*3;

        #pragma unroll
        for (int kc = 0; kc < 2; kc++) {
            const uint32_t kb = (uint32_t)(kc * 32);
            unsigned ah[2][4], al[2][4];
            #pragma unroll
            for (int mf = 0; mf < 2; mf++) {
                uint32_t ao = arow[mf] + ((kb + acb) ^ axm[mf]);
                ldsm4(ah[mf], sAh + ao);
                ldsm4(al[mf], sAl + ao);
            }
            #pragma unroll
            for (int p = 0; p < 4; p++) {
                unsigned bh4[4], bl4[4];
                uint32_t bo = brow[p] + ((kb + bcb) ^ bxm[p]);
                ldsm4(bh4, sBh + bo);
                ldsm4(bl4, sBl + bo);
                #pragma unroll
                for (int mf = 0; mf < 2; mf++) {
                    mma16816(acc[mf][2*p],     ah[mf], bh4);
                    mma16816(acc[mf][2*p + 1], ah[mf], bh4 + 2);
                    mma16816(acc[mf][2*p],     al[mf], bh4);
                    mma16816(acc[mf][2*p + 1], al[mf], bh4 + 2);
                    mma16816(acc[mf][2*p],     ah[mf], bl4);
                    mma16816(acc[mf][2*p + 1], ah[mf], bl4 + 2);
                }
            }
        }
        __syncthreads();
        stage = (stage + 1) % 3;
    }

    const int er = by * 128 + wm * 32 + (lane >> 2);
    const int ec = bx * 128 + wn * 64 + (lane & 3) * 2;
    #pragma unroll
    for (int mf = 0; mf < 2; mf++) {
        #pragma unroll
        for (int nf = 0; nf < 8; nf++) {
            int c = ec + nf * 8;
            float b0 = bias[c], b1 = bias[c + 1];
            float sc = (c < DD) ? 0.125f : 1.0f;
            #pragma unroll
            for (int half = 0; half < 2; half++) {
                int r = er + mf * 16 + half * 8;
                float v0 = (acc[mf][nf][half * 2 + 0] + b0) * sc;
                float v1 = (acc[mf][nf][half * 2 + 1] + b1) * sc;
                bf16 h0,h1,l0,l1;
                split2(v0,h0,l0); split2(v1,h1,l1);
                bf162 th; th.x = h0; th.y = h1;
                bf162 tl; tl.x = l0; tl.y = l1;
                *(bf162*)(Oh + (size_t)r * N + c) = th;
                *(bf162*)(Ol + (size_t)r * N + c) = tl;
            }
        }
    }
}

// ---------------------------------------------------------------------------
// 2-term split-fp16 HMMA GEMM: C = (Ah + Al) @ B16
// A fp16 hi/lo [M][K]; B single fp16 [N][K]. 2/3 the MMA work of 3-term.
// EPI: 1 = bias+gelu -> fp16 hi/lo    2 = bias+residual -> fp32
// ---------------------------------------------------------------------------
#define EPI_GELU16 1
#define EPI_RES32  2

#define STG2_BYTES (3*TILE_BYTES)   // Ah, Al, B = 24KB
#define GEMM2_SMEM (3*STG2_BYTES)   // 73728 B

template <int EPI>
__global__ __launch_bounds__(256, 2)
void gemm_f16(const __half* __restrict__ Ah, const __half* __restrict__ Al,
              const __half* __restrict__ Bm,
              const float* __restrict__ bias, const float* __restrict__ Rm,
              float* __restrict__ Cf, __half* __restrict__ Oh,
              __half* __restrict__ Ol, int M, int N, int K)
{
    extern __shared__ bf16 sm[];
    const int tid = threadIdx.x;
    const int bx = blockIdx.x, by = blockIdx.y;
    const int warp = tid >> 5, lane = tid & 31;
    const int wm = warp >> 1, wn = warp & 1;

    const int lrow = tid >> 1;
    const int lhalf = (tid & 1);
    const __half* gAh = Ah + (size_t)(by * 128 + lrow) * K + lhalf * 16;
    const __half* gAl = Al + (size_t)(by * 128 + lrow) * K + lhalf * 16;
    const __half* gB  = Bm + (size_t)(bx * 128 + lrow) * K + lhalf * 16;
    const uint32_t sbase = cvta_s(sm);
    const uint32_t lxm = (uint32_t)((lrow & 6) << 3);
    const uint32_t lso0 = lrow * 64 + ((lhalf * 32)      ^ lxm);
    const uint32_t lso1 = lrow * 64 + ((lhalf * 32 + 16) ^ lxm);

    float acc[2][8][4];
    #pragma unroll
    for (int i = 0; i < 2; i++)
        #pragma unroll
        for (int j = 0; j < 8; j++)
            #pragma unroll
            for (int q = 0; q < 4; q++) acc[i][j][q] = 0.0f;

    const int a_r = (lane & 7) + ((lane >> 3) & 1) * 8;
    const int a_c = (lane >> 4) * 8;
    const int b_r = (lane & 7) + (lane >> 4) * 8;
    const int b_c = ((lane >> 3) & 1) * 8;

    uint32_t arow[2], axm[2];
    #pragma unroll
    for (int mf = 0; mf < 2; mf++) {
        int r = wm*32 + mf*16 + a_r;
        arow[mf] = (uint32_t)r * 64;
        axm[mf]  = (uint32_t)((r & 6) << 3);
    }
    uint32_t brow[4], bxm[4];
    #pragma unroll
    for (int p = 0; p < 4; p++) {
        int r = wn*64 + p*16 + b_r;
        brow[p] = (uint32_t)r * 64;
        bxm[p]  = (uint32_t)((r & 6) << 3);
    }
    const uint32_t acb = (uint32_t)(a_c * 2);
    const uint32_t bcb = (uint32_t)(b_c * 2);

    const int T = K / 32;

    auto issue = [&](int s, int kk) {
        uint32_t st = sbase + (uint32_t)s * STG2_BYTES;
        cp16(st + lso0,                gAh + kk);
        cp16(st + lso1,                gAh + kk + 8);
        cp16(st + TILE_BYTES   + lso0, gAl + kk);
        cp16(st + TILE_BYTES   + lso1, gAl + kk + 8);
        cp16(st + TILE_BYTES*2 + lso0, gB  + kk);
        cp16(st + TILE_BYTES*2 + lso1, gB  + kk + 8);
        asm volatile("cp.async.commit_group;");
    };

    issue(0, 0);
    if (T > 1) issue(1, 32);

    int stage = 0;
    for (int t = 0; t < T; t++) {
        if (t + 2 < T) {
            issue((stage + 2) % 3, (t + 2) * 32);
            asm volatile("cp.async.wait_group 2;");
        } else if (t + 1 < T) {
            asm volatile("cp.async.wait_group 1;");
        } else {
            asm volatile("cp.async.wait_group 0;");
        }
        __syncthreads();

        const uint32_t st  = sbase + (uint32_t)stage * STG2_BYTES;
        const uint32_t sAh = st;
        const uint32_t sAl = st + TILE_BYTES;
        const uint32_t sB  = st + TILE_BYTES*2;

        #pragma unroll
        for (int kc = 0; kc < 2; kc++) {
            const uint32_t kb = (uint32_t)(kc * 32);
            unsigned ah[2][4], al[2][4];
            #pragma unroll
            for (int mf = 0; mf < 2; mf++) {
                uint32_t ao = arow[mf] + ((kb + acb) ^ axm[mf]);
                ldsm4(ah[mf], sAh + ao);
                ldsm4(al[mf], sAl + ao);
            }
            #pragma unroll
            for (int p = 0; p < 4; p++) {
                unsigned b4[4];
                uint32_t bo = brow[p] + ((kb + bcb) ^ bxm[p]);
                ldsm4(b4, sB + bo);
                #pragma unroll
                for (int mf = 0; mf < 2; mf++) {
                    mma16816h(acc[mf][2*p],     ah[mf], b4);
                    mma16816h(acc[mf][2*p + 1], ah[mf], b4 + 2);
                    mma16816h(acc[mf][2*p],     al[mf], b4);
                    mma16816h(acc[mf][2*p + 1], al[mf], b4 + 2);
                }
            }
        }
        __syncthreads();
        stage = (stage + 1) % 3;
    }

    const int er = by * 128 + wm * 32 + (lane >> 2);
    const int ec = bx * 128 + wn * 64 + (lane & 3) * 2;
    #pragma unroll
    for (int mf = 0; mf < 2; mf++) {
        #pragma unroll
        for (int nf = 0; nf < 8; nf++) {
            int c = ec + nf * 8;
            float b0 = bias[c], b1 = bias[c + 1];
            #pragma unroll
            for (int half = 0; half < 2; half++) {
                int r = er + mf * 16 + half * 8;
                float v0 = acc[mf][nf][half * 2 + 0] + b0;
                float v1 = acc[mf][nf][half * 2 + 1] + b1;
                if (EPI == EPI_GELU16) {
                    v0 = gelu_exact(v0); v1 = gelu_exact(v1);
                    __half h0,h1,l0,l1;
                    split2h(v0,h0,l0); split2h(v1,h1,l1);
                    *(__half2*)(Oh + (size_t)r * N + c) = __halves2half2(h0, h1);
                    *(__half2*)(Ol + (size_t)r * N + c) = __halves2half2(l0, l1);
                } else {
                    float2 rr = *(const float2*)(Rm + (size_t)r * N + c);
                    v0 += rr.x; v1 += rr.y;
                    float2 o; o.x = v0; o.y = v1;
                    *(float2*)(Cf + (size_t)r * N + c) = o;
                }
            }
        }
    }
}

// ---------------------------------------------------------------------------
// Tensor-core flash attention, split-bf16 inputs; z output now fp16 hi/lo.
// ---------------------------------------------------------------------------
#define AQS   72
#define ATILE (64*AQS)
#define ATTN_SMEM ((2*ATILE + 8*ATILE) * 2)

__global__ __launch_bounds__(128, 2)
void attn_mma(const bf16* __restrict__ qkvh, const bf16* __restrict__ qkvl,
              __half* __restrict__ zh, __half* __restrict__ zl)
{
    extern __shared__ bf16 smb[];
    const uint32_t sbase = cvta_s(smb);
    const int tid  = threadIdx.x;
    const int warp = tid >> 5, lane = tid & 31;
    const int qt = blockIdx.x;
    const int bh = blockIdx.y;
    const int h  = bh & 15;
    const int hcol = h * DHH;
    const int tokbase = (bh >> 4) * SS;

    const uint32_t oQh = 0, oQl = ATILE;
    auto stageoff = [](int s) { return (uint32_t)(2*ATILE + s*4*ATILE); };

    const int ldrow = tid >> 1;
    const int ldc0  = (tid & 1) * 32;
    auto ld_tensor = [&](uint32_t selems, const bf16* g, int tok0, int coff) {
        const bf16* gp = g + (size_t)(tok0 + ldrow) * (3*DD) + coff + ldc0;
        uint32_t sp = sbase + (selems + ldrow * AQS + ldc0) * 2;
        cp16(sp,      gp);
        cp16(sp + 16, gp + 8);
        cp16(sp + 32, gp + 16);
        cp16(sp + 48, gp + 24);
    };
    auto issue_kv = [&](int s, int kt) {
        int tok0 = tokbase + kt * 64;
        uint32_t so = stageoff(s);
        ld_tensor(so,           qkvh, tok0, DD   + hcol);
        ld_tensor(so + ATILE,   qkvl, tok0, DD   + hcol);
        ld_tensor(so + 2*ATILE, qkvh, tok0, 2*DD + hcol);
        ld_tensor(so + 3*ATILE, qkvl, tok0, 2*DD + hcol);
        asm volatile("cp.async.commit_group;");
    };

    {
        int tok0 = tokbase + qt * 64;
        ld_tensor(oQh, qkvh, tok0, hcol);
        ld_tensor(oQl, qkvl, tok0, hcol);
        issue_kv(0, 0);
    }

    const int a_r  = (lane & 7) + ((lane >> 3) & 1) * 8;
    const int a_c  = (lane >> 4) * 8;
    const int kb_r = (lane & 7) + (lane >> 4) * 8;
    const int kb_c = ((lane >> 3) & 1) * 8;
    const int vb_r = (lane & 7) + ((lane >> 3) & 1) * 8;
    const int vb_c = (lane >> 4) * 8;

    unsigned qh[4][4], ql[4][4];
    float o[8][4];
    #pragma unroll
    for (int j = 0; j < 8; j++)
        #pragma unroll
        for (int q = 0; q < 4; q++) o[j][q] = 0.0f;
    float m0 = -INFINITY, m1 = -INFINITY, l0 = 0.0f, l1 = 0.0f;

    const int r0 = lane >> 2;
    const int colq = 2 * (lane & 3);

    for (int kt = 0; kt <= qt; kt++) {
        if (kt + 1 <= qt) {
            issue_kv((kt + 1) & 1, kt + 1);
            asm volatile("cp.async.wait_group 1;");
        } else {
            asm volatile("cp.async.wait_group 0;");
        }
        __syncthreads();

        if (kt == 0) {
            #pragma unroll
            for (int kc = 0; kc < 4; kc++) {
                uint32_t ao = ((warp*16 + a_r) * AQS + kc*16 + a_c) * 2;
                ldsm4(qh[kc], sbase + (oQh)*2 + ao);
                ldsm4(ql[kc], sbase + (oQl)*2 + ao);
            }
        }

        const uint32_t so = stageoff(kt & 1);
        const uint32_t sKh = sbase + so * 2;
        const uint32_t sKl = sbase + (so + ATILE) * 2;
        const uint32_t sVh = sbase + (so + 2*ATILE) * 2;
        const uint32_t sVl = sbase + (so + 3*ATILE) * 2;

        float s[8][4];
        #pragma unroll
        for (int j = 0; j < 8; j++)
            #pragma unroll
            for (int q = 0; q < 4; q++) s[j][q] = 0.0f;

        #pragma unroll
        for (int jp = 0; jp < 4; jp++) {
            #pragma unroll
            for (int kc = 0; kc < 4; kc++) {
                unsigned kh4[4], kl4[4];
                uint32_t ko = ((jp*16 + kb_r) * AQS + kc*16 + kb_c) * 2;
                ldsm4(kh4, sKh + ko);
                ldsm4(kl4, sKl + ko);
                mma16816(s[2*jp],   qh[kc], kh4);
                mma16816(s[2*jp+1], qh[kc], kh4 + 2);
                mma16816(s[2*jp],   ql[kc], kh4);
                mma16816(s[2*jp+1], ql[kc], kh4 + 2);
                mma16816(s[2*jp],   qh[kc], kl4);
                mma16816(s[2*jp+1], qh[kc], kl4 + 2);
            }
        }

        if (kt == qt) {
            const int rg0 = warp*16 + r0;
            #pragma unroll
            for (int j = 0; j < 8; j++) {
                int cg = j*8 + colq;
                if (cg     > rg0) s[j][0] = -1e30f;
                if (cg + 1 > rg0) s[j][1] = -1e30f;
                if (cg     > rg0 + 8) s[j][2] = -1e30f;
                if (cg + 1 > rg0 + 8) s[j][3] = -1e30f;
            }
        }

        float vmax0 = -INFINITY, vmax1 = -INFINITY;
        #pragma unroll
        for (int j = 0; j < 8; j++) {
            vmax0 = fmaxf(vmax0, fmaxf(s[j][0], s[j][1]));
            vmax1 = fmaxf(vmax1, fmaxf(s[j][2], s[j][3]));
        }
        vmax0 = fmaxf(vmax0, __shfl_xor_sync(0xffffffffu, vmax0, 1));
        vmax0 = fmaxf(vmax0, __shfl_xor_sync(0xffffffffu, vmax0, 2));
        vmax1 = fmaxf(vmax1, __shfl_xor_sync(0xffffffffu, vmax1, 1));
        vmax1 = fmaxf(vmax1, __shfl_xor_sync(0xffffffffu, vmax1, 2));

        float mn0 = fmaxf(m0, vmax0), mn1 = fmaxf(m1, vmax1);
        float f0 = __expf(m0 - mn0), f1 = __expf(m1 - mn1);
        m0 = mn0; m1 = mn1;

        float rs0 = 0.0f, rs1 = 0.0f;
        #pragma unroll
        for (int j = 0; j < 8; j++) {
            s[j][0] = __expf(s[j][0] - mn0);
            s[j][1] = __expf(s[j][1] - mn0);
            s[j][2] = __expf(s[j][2] - mn1);
            s[j][3] = __expf(s[j][3] - mn1);
            rs0 += s[j][0] + s[j][1];
            rs1 += s[j][2] + s[j][3];
        }
        rs0 += __shfl_xor_sync(0xffffffffu, rs0, 1);
        rs0 += __shfl_xor_sync(0xffffffffu, rs0, 2);
        rs1 += __shfl_xor_sync(0xffffffffu, rs1, 1);
        rs1 += __shfl_xor_sync(0xffffffffu, rs1, 2);
        l0 = l0 * f0 + rs0;
        l1 = l1 * f1 + rs1;

        #pragma unroll
        for (int j = 0; j < 8; j++) {
            o[j][0] *= f0; o[j][1] *= f0;
            o[j][2] *= f1; o[j][3] *= f1;
        }

        unsigned ph[4][4], pl[4][4];
        #pragma unroll
        for (int jc = 0; jc < 4; jc++) {
            const int j0 = 2*jc, j1 = 2*jc + 1;
            #define SPLITPAIR(a, b, HI, LOI)                       \
                {  bf16 _h0,_l0,_h1,_l1;                           \
                   split2(a,_h0,_l0); split2(b,_h1,_l1);           \
                   HI  = packbf(__bfloat162float(_h0), __bfloat162float(_h1)); \
                   LOI = packbf(__bfloat162float(_l0), __bfloat162float(_l1)); }
            SPLITPAIR(s[j0][0], s[j0][1], ph[jc][0], pl[jc][0]);
            SPLITPAIR(s[j0][2], s[j0][3], ph[jc][1], pl[jc][1]);
            SPLITPAIR(s[j1][0], s[j1][1], ph[jc][2], pl[jc][2]);
            SPLITPAIR(s[j1][2], s[j1][3], ph[jc][3], pl[jc][3]);
            #undef SPLITPAIR
        }

        #pragma unroll
        for (int jc = 0; jc < 4; jc++) {
            #pragma unroll
            for (int np = 0; np < 4; np++) {
                unsigned vh4[4], vl4[4];
                uint32_t vo = ((jc*16 + vb_r) * AQS + np*16 + vb_c) * 2;
                ldsm4t(vh4, sVh + vo);
                ldsm4t(vl4, sVl + vo);
                mma16816(o[2*np],   ph[jc], vh4);
                mma16816(o[2*np+1], ph[jc], vh4 + 2);
                mma16816(o[2*np],   pl[jc], vh4);
                mma16816(o[2*np+1], pl[jc], vh4 + 2);
                mma16816(o[2*np],   ph[jc], vl4);
                mma16816(o[2*np+1], ph[jc], vl4 + 2);
            }
        }
        __syncthreads();
    }

    // ---- finalize: z = O / l, split to fp16 hi/lo ----
    const float il0 = 1.0f / l0, il1 = 1.0f / l1;
    const int row0 = tokbase + qt*64 + warp*16 + r0;
    #pragma unroll
    for (int j = 0; j < 8; j++) {
        int c = hcol + j*8 + colq;
        float a0 = o[j][0] * il0, a1 = o[j][1] * il0;
        float b0 = o[j][2] * il1, b1 = o[j][3] * il1;
        __half h0,lo0,h1,lo1;
        split2h(a0,h0,lo0); split2h(a1,h1,lo1);
        *(__half2*)(zh + (size_t)row0 * DD + c) = __halves2half2(h0, h1);
        *(__half2*)(zl + (size_t)row0 * DD + c) = __halves2half2(lo0, lo1);
        split2h(b0,h0,lo0); split2h(b1,h1,lo1);
        *(__half2*)(zh + (size_t)(row0 + 8) * DD + c) = __halves2half2(h0, h1);
        *(__half2*)(zl + (size_t)(row0 + 8) * DD + c) = __halves2half2(lo0, lo1);
    }
}

// ---------------------------------------------------------------------------
// Host launcher
// ---------------------------------------------------------------------------
extern "C" void kernel_launch(void* const* d_in, const int* in_sizes, int n_in,
                              void* d_out, int out_size)
{
    (void)in_sizes; (void)n_in; (void)out_size;
    const float* resid = (const float*)d_in[0];
    const float* ln1w  = (const float*)d_in[1];
    const float* ln1b  = (const float*)d_in[2];
    const float* WQ    = (const float*)d_in[3];
    const float* bQ    = (const float*)d_in[4];
    const float* WK    = (const float*)d_in[5];
    const float* bK    = (const float*)d_in[6];
    const float* WV    = (const float*)d_in[7];
    const float* bV    = (const float*)d_in[8];
    const float* WO    = (const float*)d_in[9];
    const float* bO    = (const float*)d_in[10];
    const float* ln2w  = (const float*)d_in[11];
    const float* ln2b  = (const float*)d_in[12];
    const float* Win   = (const float*)d_in[13];
    const float* bin   = (const float*)d_in[14];
    const float* Wout  = (const float*)d_in[15];
    const float* bout  = (const float*)d_in[16];

    float *mid, *biasqkv;
    bf16 *xh, *xl, *qkvh, *qkvl, *acth, *actl, *wh, *wl;
    cudaGetSymbolAddress((void**)&mid,   g_mid);
    cudaGetSymbolAddress((void**)&biasqkv, g_bias);
    cudaGetSymbolAddress((void**)&xh,    g_xh);
    cudaGetSymbolAddress((void**)&xl,    g_xl);
    cudaGetSymbolAddress((void**)&qkvh,  g_qkvh);
    cudaGetSymbolAddress((void**)&qkvl,  g_qkvl);
    cudaGetSymbolAddress((void**)&acth,  g_acth);
    cudaGetSymbolAddress((void**)&actl,  g_actl);
    cudaGetSymbolAddress((void**)&wh,    g_wh);
    cudaGetSymbolAddress((void**)&wl,    g_wl);

    // fp16 aliases (same 2-byte storage)
    __half* x16h  = (__half*)xh;
    __half* x16l  = (__half*)xl;
    __half* a16h  = (__half*)acth;
    __half* a16l  = (__half*)actl;
    __half* w16   = (__half*)wh;

    cudaFuncSetAttribute(attn_mma, cudaFuncAttributeMaxDynamicSharedMemorySize,
                         ATTN_SMEM);
    cudaFuncSetAttribute(gemm_bf16_qkv,
                         cudaFuncAttributeMaxDynamicSharedMemorySize, GEMM_SMEM);
    cudaFuncSetAttribute(gemm_f16<EPI_GELU16>,
                         cudaFuncAttributeMaxDynamicSharedMemorySize, GEMM2_SMEM);
    cudaFuncSetAttribute(gemm_f16<EPI_RES32>,
                         cudaFuncAttributeMaxDynamicSharedMemorySize, GEMM2_SMEM);

    dim3 tb(32, 8);

    // 1) LN1 -> bf16 split
    ln_split_kernel<0><<<NTOK, 256>>>(resid, ln1w, ln1b, xh, xl);

    // 2) fused QKV (3-term bf16, Q prescaled by 1/8)
    concat_bias<<<12, 256>>>(bQ, bK, bV, biasqkv);
    tsplit_qkv<<<dim3(DHH/32, DD/32, 48), tb>>>(WQ, WK, WV, wh, wl);
    gemm_bf16_qkv<<<dim3(3*DD/128, NTOK/128), 256, GEMM_SMEM>>>(
        xh, xl, wh, wl, biasqkv, qkvh, qkvl, NTOK, 3*DD, DD);

    // 3) attention -> z fp16 split (into x16h/x16l)
    dim3 ga(SS / 64, BB * HH);
    attn_mma<<<ga, 128, ATTN_SMEM>>>(qkvh, qkvl, x16h, x16l);

    // 4) O-projection + residual -> mid (2-term fp16)
    tsplit16_kernel<<<dim3(DD/32, DD/32), tb>>>(WO, w16, DD, DD);
    gemm_f16<EPI_RES32><<<dim3(DD/128, NTOK/128), 256, GEMM2_SMEM>>>(
        x16h, x16l, w16, bO, resid, mid, nullptr, nullptr, NTOK, DD, DD);

    // 5) LN2 -> fp16 split
    ln_split_kernel<1><<<NTOK, 256>>>(mid, ln2w, ln2b, x16h, x16l);

    // 6) MLP in + exact GELU -> fp16 split act (2-term fp16)
    tsplit16_kernel<<<dim3(DMM/32, DD/32), tb>>>(Win, w16, DD, DMM);
    gemm_f16<EPI_GELU16><<<dim3(DMM/128, NTOK/128), 256, GEMM2_SMEM>>>(
        x16h, x16l, w16, bin, nullptr, nullptr, a16h, a16l, NTOK, DMM, DD);

    // 7) MLP out + bias + residual -> d_out (2-term fp16)
    tsplit16_kernel<<<dim3(DD/32, DMM/32), tb>>>(Wout, w16, DMM, DD);
    gemm_f16<EPI_RES32><<<dim3(DD/128, NTOK/128), 256, GEMM2_SMEM>>>(
        a16h, a16l, w16, bout, mid, (float*)d_out, nullptr, nullptr,
        NTOK, DD, DMM);
}